// round 3
// baseline (speedup 1.0000x reference)
#include <cuda_runtime.h>
#include <cstdint>

#define D_DIM 1024
#define K_TOP 307

// ---------------------------------------------------------------------------
// Fast-math-immune sigmoid: 1/(1+exp(-z)) with Cody-Waite reduction + poly.
// ~2-3 ulp, monotone; avoids expf being swapped for __expf under fast math.
// ---------------------------------------------------------------------------
__device__ __forceinline__ float sigmoid_acc(float z) {
    float x = -z;
    // clamp to keep 2^n scaling in normal range; tails round to 0/1 anyway
    x = fminf(fmaxf(x, -87.0f), 87.0f);
    float t = x * 1.4426950408889634f;
    float n = rintf(t);
    float r = fmaf(n, -0.693145751953125f, x);       // ln2_hi
    r = fmaf(n, -1.42860676533018687e-06f, r);       // ln2_lo
    // exp(r) = 1 + r + r^2 * P(r)   (cephes coefficients)
    float p = 1.9875691500e-4f;
    p = fmaf(p, r, 1.3981999507e-3f);
    p = fmaf(p, r, 8.3333331174e-3f);
    p = fmaf(p, r, 4.1665795894e-2f);
    p = fmaf(p, r, 1.6666665459e-1f);
    p = fmaf(p, r, 5.0000001201e-1f);
    float y = fmaf(r * r, p, r) + 1.0f;
    int   i  = (int)n;
    float sc = __int_as_float((i + 127) << 23);
    float e  = y * sc;                                // exp(-z)
    return 1.0f / (1.0f + e);
}

// ---------------------------------------------------------------------------
// Kernel A: C[n,e] = sigmoid(sum_k X[n,k]*W[e,k] + b[e]) -> S (fp32)
// 128x128x8 tile, 256 threads, 8x8 microtile, double-buffered smem.
// ---------------------------------------------------------------------------
__global__ __launch_bounds__(256, 2)
void gemm_sigmoid_kernel(const float* __restrict__ X, const float* __restrict__ W,
                         const float* __restrict__ bias, float* __restrict__ S) {
    __shared__ float As[2][8][128];
    __shared__ float Bs[2][8][128];

    const int tid  = threadIdx.x;
    const int brow = blockIdx.y << 7;
    const int bcol = blockIdx.x << 7;

    // loaders: 256 threads, each a float4: row = tid/2, k-chunk = (tid&1)*4
    const int lrow = tid >> 1;
    const int lk   = (tid & 1) << 2;
    const float* ap = X + (size_t)(brow + lrow) * D_DIM + lk;
    const float* bp = W + (size_t)(bcol + lrow) * D_DIM + lk;

    {
        float4 a4 = *(const float4*)ap;
        float4 b4 = *(const float4*)bp;
        As[0][lk + 0][lrow] = a4.x; As[0][lk + 1][lrow] = a4.y;
        As[0][lk + 2][lrow] = a4.z; As[0][lk + 3][lrow] = a4.w;
        Bs[0][lk + 0][lrow] = b4.x; Bs[0][lk + 1][lrow] = b4.y;
        Bs[0][lk + 2][lrow] = b4.z; Bs[0][lk + 3][lrow] = b4.w;
    }
    __syncthreads();

    const int ty = tid >> 4;   // 0..15
    const int tx = tid & 15;   // 0..15

    float acc[8][8];
#pragma unroll
    for (int i = 0; i < 8; i++)
#pragma unroll
        for (int j = 0; j < 8; j++) acc[i][j] = 0.0f;

    int buf = 0;
    for (int k0 = 0; k0 < D_DIM; k0 += 8) {
        float4 an, bn;
        const bool more = (k0 + 8) < D_DIM;
        if (more) {
            an = *(const float4*)(ap + k0 + 8);
            bn = *(const float4*)(bp + k0 + 8);
        }
#pragma unroll
        for (int kk = 0; kk < 8; kk++) {
            float4 a0 = *(const float4*)&As[buf][kk][(ty << 2)];
            float4 a1 = *(const float4*)&As[buf][kk][64 + (ty << 2)];
            float4 c0 = *(const float4*)&Bs[buf][kk][(tx << 2)];
            float4 c1 = *(const float4*)&Bs[buf][kk][64 + (tx << 2)];
            float ar[8] = {a0.x, a0.y, a0.z, a0.w, a1.x, a1.y, a1.z, a1.w};
            float br[8] = {c0.x, c0.y, c0.z, c0.w, c1.x, c1.y, c1.z, c1.w};
#pragma unroll
            for (int i = 0; i < 8; i++)
#pragma unroll
                for (int j = 0; j < 8; j++)
                    acc[i][j] = fmaf(ar[i], br[j], acc[i][j]);
        }
        if (more) {
            buf ^= 1;
            As[buf][lk + 0][lrow] = an.x; As[buf][lk + 1][lrow] = an.y;
            As[buf][lk + 2][lrow] = an.z; As[buf][lk + 3][lrow] = an.w;
            Bs[buf][lk + 0][lrow] = bn.x; Bs[buf][lk + 1][lrow] = bn.y;
            Bs[buf][lk + 2][lrow] = bn.z; Bs[buf][lk + 3][lrow] = bn.w;
            __syncthreads();
        }
    }

    // epilogue: + bias, sigmoid, store
    float4 bb0 = *(const float4*)&bias[bcol + (tx << 2)];
    float4 bb1 = *(const float4*)&bias[bcol + 64 + (tx << 2)];
    float bv[8] = {bb0.x, bb0.y, bb0.z, bb0.w, bb1.x, bb1.y, bb1.z, bb1.w};

#pragma unroll
    for (int i = 0; i < 8; i++) {
        const int r = brow + ((i < 4) ? ((ty << 2) + i) : (64 + (ty << 2) + i - 4));
        float4 o0, o1;
        o0.x = sigmoid_acc(acc[i][0] + bv[0]);
        o0.y = sigmoid_acc(acc[i][1] + bv[1]);
        o0.z = sigmoid_acc(acc[i][2] + bv[2]);
        o0.w = sigmoid_acc(acc[i][3] + bv[3]);
        o1.x = sigmoid_acc(acc[i][4] + bv[4]);
        o1.y = sigmoid_acc(acc[i][5] + bv[5]);
        o1.z = sigmoid_acc(acc[i][6] + bv[6]);
        o1.w = sigmoid_acc(acc[i][7] + bv[7]);
        *(float4*)&S[(size_t)r * D_DIM + bcol + (tx << 2)]      = o0;
        *(float4*)&S[(size_t)r * D_DIM + bcol + 64 + (tx << 2)] = o1;
    }
}

// ---------------------------------------------------------------------------
// Kernel B: per-row exact top-K via radix-select on the sigmoid values.
// Positive floats -> uint bit pattern preserves order. Tie-break = lowest
// index (matches jax.lax.top_k). One block (256 threads) per row; each
// thread owns 4 contiguous elements (index order preserved for the tie scan).
// ---------------------------------------------------------------------------
__global__ __launch_bounds__(256)
void topk_mask_kernel(const float* __restrict__ X, const float* __restrict__ S,
                      float* __restrict__ O) {
    const int row = blockIdx.x;
    const int t   = threadIdx.x;
    const size_t base = (size_t)row * D_DIM;

    const uint4 u = ((const uint4*)(S + base))[t];

    __shared__ int hist[256];
    __shared__ int sscan[256];
    __shared__ uint32_t sh_pref;
    __shared__ int sh_need;
    __shared__ int wsum[8];

    uint32_t prefix = 0;
    int need = K_TOP;
    const uint32_t dmask[4] = {0u, 0xFF000000u, 0xFFFF0000u, 0xFFFFFF00u};

#pragma unroll
    for (int p = 0; p < 4; p++) {
        const int shift = 24 - (p << 3);
        const uint32_t dm = dmask[p];
        hist[t] = 0;
        __syncthreads();
        if ((u.x & dm) == prefix) atomicAdd(&hist[(u.x >> shift) & 255], 1);
        if ((u.y & dm) == prefix) atomicAdd(&hist[(u.y >> shift) & 255], 1);
        if ((u.z & dm) == prefix) atomicAdd(&hist[(u.z >> shift) & 255], 1);
        if ((u.w & dm) == prefix) atomicAdd(&hist[(u.w >> shift) & 255], 1);
        __syncthreads();
        sscan[t] = hist[t];
        __syncthreads();
        // suffix (descending) inclusive scan: sscan[d] = # candidates with digit >= d
#pragma unroll
        for (int off = 1; off < 256; off <<= 1) {
            int v = (t + off < 256) ? sscan[t + off] : 0;
            __syncthreads();
            sscan[t] += v;
            __syncthreads();
        }
        const int ge  = sscan[t];
        const int nxt = (t < 255) ? sscan[t + 1] : 0;
        if (ge >= need && nxt < need) {
            sh_pref = prefix | ((uint32_t)t << shift);
            sh_need = need - nxt;
        }
        __syncthreads();
        prefix = sh_pref;
        need   = sh_need;
        __syncthreads();
    }

    const uint32_t T = prefix;  // exact K-th largest value (bit pattern)

    // index-ordered rank among elements == T
    const int e0 = (u.x == T), e1 = (u.y == T), e2 = (u.z == T), e3 = (u.w == T);
    const int cnt = e0 + e1 + e2 + e3;
    const int lane = t & 31, wid = t >> 5;
    int incl = cnt;
#pragma unroll
    for (int off = 1; off < 32; off <<= 1) {
        int v = __shfl_up_sync(0xffffffffu, incl, off);
        if (lane >= off) incl += v;
    }
    if (lane == 31) wsum[wid] = incl;
    __syncthreads();
    if (t == 0) {
        int s = 0;
#pragma unroll
        for (int i = 0; i < 8; i++) { int v = wsum[i]; wsum[i] = s; s += v; }
    }
    __syncthreads();
    int rank = wsum[wid] + (incl - cnt);  // exclusive prefix before my first elem

    const float4 xv = ((const float4*)(X + base))[t];
    float4 o;
    const bool s0 = (u.x > T) || (e0 && rank < need); rank += e0;
    const bool s1 = (u.y > T) || (e1 && rank < need); rank += e1;
    const bool s2 = (u.z > T) || (e2 && rank < need); rank += e2;
    const bool s3 = (u.w > T) || (e3 && rank < need);
    o.x = s0 ? xv.x : 0.0f;
    o.y = s1 ? xv.y : 0.0f;
    o.z = s2 ? xv.z : 0.0f;
    o.w = s3 ? xv.w : 0.0f;
    ((float4*)(O + base))[t] = o;
}

// ---------------------------------------------------------------------------
extern "C" void kernel_launch(void* const* d_in, const int* in_sizes, int n_in,
                              void* d_out, int out_size) {
    const float* X = (const float*)d_in[0];  // [N, 1024]
    const float* W = (const float*)d_in[1];  // [1024, 1024]
    const float* b = (const float*)d_in[2];  // [1024]
    float* out = (float*)d_out;              // [2, N, 1024]: (mask*x, scores)

    const int N = in_sizes[0] / D_DIM;
    float* S = out + (size_t)N * D_DIM;      // feature_scores half

    dim3 grid(D_DIM / 128, N / 128);
    gemm_sigmoid_kernel<<<grid, 256>>>(X, W, b, S);
    topk_mask_kernel<<<N, 256>>>(X, S, out);
}